// round 16
// baseline (speedup 1.0000x reference)
#include <cuda_runtime.h>
#include <cuda_fp16.h>
#include <math.h>
#include <stdint.h>

#define NSLICE 16
#define LSEQ   2048
#define DLLM   768
#define EDIM   64
#define EPS    1e-5f
#define NQT    16
#define QLOG2SCALE (0.125f * 1.4426950408889634f)

// ---------------- device scratch ----------------
__device__ float g_o[NSLICE*LSEQ*EDIM];
__device__ __half g_qf[NSLICE*LSEQ*EDIM];    // q*0.125*log2e fp16
__device__ __half g_kf[NSLICE*LSEQ*EDIM];    // k fp16
__device__ __half g_vt[NSLICE*EDIM*LSEQ];    // V^T [s][e][key] fp16
__device__ __half g_wf[3*EDIM*DLLM];         // W^T [w][n][k] fp16
__device__ float2 g_part[NSLICE*NQT];

// ---------------- helpers (validated) ----------------
__device__ __forceinline__ uint32_t smem_u32(const void* p) {
    uint32_t a;
    asm("{ .reg .u64 t; cvta.to.shared.u64 t, %1; cvt.u32.u64 %0, t; }" : "=r"(a) : "l"(p));
    return a;
}
__device__ __forceinline__ void ldsm4(uint32_t* r, uint32_t addr) {
    asm volatile("ldmatrix.sync.aligned.m8n8.x4.shared.b16 {%0,%1,%2,%3}, [%4];"
                 : "=r"(r[0]), "=r"(r[1]), "=r"(r[2]), "=r"(r[3]) : "r"(addr) : "memory");
}
__device__ __forceinline__ uint32_t ldsm_addr(uint32_t base, int row0, int kbyte,
                                              int pitch, int lane) {
    return base + (row0 + (lane & 15)) * pitch + kbyte + (lane >> 4) * 16;
}
__device__ __forceinline__ void mma_f16(float* d, const uint32_t* a,
                                        uint32_t b0, uint32_t b1) {
    asm volatile("mma.sync.aligned.m16n8k16.row.col.f32.f16.f16.f32 "
        "{%0,%1,%2,%3}, {%4,%5,%6,%7}, {%8,%9}, {%0,%1,%2,%3};"
        : "+f"(d[0]), "+f"(d[1]), "+f"(d[2]), "+f"(d[3])
        : "r"(a[0]), "r"(a[1]), "r"(a[2]), "r"(a[3]), "r"(b0), "r"(b1));
}
__device__ __forceinline__ uint32_t pack_h2(float x0, float x1) {
    __half2 h = __floats2half2_rn(x0, x1);
    return *reinterpret_cast<uint32_t*>(&h);
}
__device__ __forceinline__ uint32_t pack_exp2(float x0, float x1) {
    __half2 h = h2exp2(__floats2half2_rn(x0, x1));
    return *reinterpret_cast<uint32_t*>(&h);
}
#define CP_ASYNC(dst, src) \
    asm volatile("cp.async.cg.shared.global [%0], [%1], 16;" :: "r"(dst), "l"(src) : "memory")
#define CP_COMMIT() asm volatile("cp.async.commit_group;" ::: "memory")
#define CP_WAIT(n)  asm volatile("cp.async.wait_group %0;" :: "n"(n) : "memory")

// ---------------- kernel 0: W^T fp16 ----------------
__global__ void wsplit_kernel(const float* __restrict__ Wq,
                              const float* __restrict__ Wk,
                              const float* __restrict__ Wv) {
    int idx = blockIdx.x * 256 + threadIdx.x;
    if (idx >= 3 * EDIM * DLLM) return;
    int w = idx / (EDIM * DLLM), rem = idx % (EDIM * DLLM);
    int n = rem / DLLM, k = rem % DLLM;
    const float* W = (w == 0) ? Wq : (w == 1) ? Wk : Wv;
    g_wf[idx] = __float2half_rn(W[k * EDIM + n]);
}

// ----------------------------------------------------------------------------
// Kernel 1: projection fp16; X converted at LDG time (xr = packed uint2,
// 16 regs); 3 CTAs/SM.
// ----------------------------------------------------------------------------
#define PA0 0
#define PA1 18432
#define PB0 36864
#define PB1 46080
#define PR_SMEM 55296

__global__ __launch_bounds__(256, 3)
void proj_kernel(const float* __restrict__ X,
                 const float* __restrict__ bq, const float* __restrict__ bk,
                 const float* __restrict__ bv)
{
    extern __shared__ char smem[];
    const uint32_t sb = smem_u32(smem);
    const int tid = threadIdx.x, wid = tid >> 5, lane = tid & 31;
    const int g = lane >> 2, tig = lane & 3;
    const int s = blockIdx.y;
    const int w = blockIdx.x % 3;
    const int row0 = (blockIdx.x / 3) * 128;
    const float* Xs = X + (size_t)s * LSEQ * DLLM + (size_t)row0 * DLLM;

    float acc[8][4];
    #pragma unroll
    for (int j = 0; j < 8; ++j)
        #pragma unroll
        for (int q = 0; q < 4; ++q) acc[j][q] = 0.f;

    // prefetch X chunk 0, converting to fp16 pairs at load time
    uint2 xr[8];
    #pragma unroll
    for (int t = 0; t < 8; ++t) {
        int f = tid + t * 256;
        int rr = f >> 4, c4 = (f & 15) * 4;
        float4 x = *reinterpret_cast<const float4*>(&Xs[(size_t)rr * DLLM + c4]);
        xr[t] = make_uint2(pack_h2(x.x, x.y), pack_h2(x.z, x.w));
    }
    #pragma unroll
    for (int t = 0; t < 2; ++t) {
        int f = tid + t * 256;
        int n = f >> 3, k8 = (f & 7) * 8;
        CP_ASYNC(sb + PB0 + n * 144 + k8 * 2,
                 g_wf + (size_t)w * EDIM * DLLM + (size_t)n * DLLM + k8);
    }
    CP_COMMIT();

    for (int chunk = 0; chunk < 12; ++chunk) {
        const int cur = chunk & 1;
        const uint32_t ab = sb + (cur ? PA1 : PA0);
        const uint32_t bb = sb + (cur ? PB1 : PB0);

        // drain converted A regs to smem
        #pragma unroll
        for (int t = 0; t < 8; ++t) {
            int f = tid + t * 256;
            int rr = f >> 4, c4 = (f & 15) * 4;
            *reinterpret_cast<uint2*>(smem + (cur ? PA1 : PA0) + rr * 144 + c4 * 2) = xr[t];
        }
        if (chunk < 11) {
            const int k0n = (chunk + 1) * 64;
            #pragma unroll
            for (int t = 0; t < 8; ++t) {
                int f = tid + t * 256;
                int rr = f >> 4, c4 = (f & 15) * 4;
                float4 x = *reinterpret_cast<const float4*>(&Xs[(size_t)rr * DLLM + k0n + c4]);
                xr[t] = make_uint2(pack_h2(x.x, x.y), pack_h2(x.z, x.w));
            }
            const uint32_t bbn = sb + (cur ? PB0 : PB1);
            #pragma unroll
            for (int t = 0; t < 2; ++t) {
                int f = tid + t * 256;
                int n = f >> 3, k8 = (f & 7) * 8;
                CP_ASYNC(bbn + n * 144 + k8 * 2,
                         g_wf + (size_t)w * EDIM * DLLM + (size_t)n * DLLM + k0n + k8);
            }
            CP_COMMIT();
            CP_WAIT(1);
        } else {
            CP_WAIT(0);
        }
        __syncthreads();

        #pragma unroll
        for (int kb = 0; kb < 4; ++kb) {
            const int kby = kb * 32;
            uint32_t aF[4];
            ldsm4(aF, ldsm_addr(ab, wid * 16, kby, 144, lane));
            #pragma unroll
            for (int ntp = 0; ntp < 4; ++ntp) {
                uint32_t bF[4];
                ldsm4(bF, ldsm_addr(bb, ntp * 16, kby, 144, lane));
                mma_f16(acc[2*ntp],   aF, bF[0], bF[2]);
                mma_f16(acc[2*ntp+1], aF, bF[1], bF[3]);
            }
        }
        __syncthreads();
    }

    const int r0 = row0 + wid * 16 + g, r1 = r0 + 8;
    const float* bias = (w == 0) ? bq : (w == 1) ? bk : bv;
    const float mscale = (w == 0) ? QLOG2SCALE : 1.f;
    #pragma unroll
    for (int j = 0; j < 8; ++j) {
        int c = tig * 2 + 8 * j;
        float b0 = bias[c], b1 = bias[c + 1];
        float v00 = acc[j][0] + b0, v01 = acc[j][1] + b1;
        float v10 = acc[j][2] + b0, v11 = acc[j][3] + b1;
        if (w < 2) {
            __half* dst = (w ? g_kf : g_qf) + (size_t)s * LSEQ * EDIM;
            *reinterpret_cast<uint32_t*>(dst + (size_t)r0 * EDIM + c) =
                pack_h2(v00 * mscale, v01 * mscale);
            *reinterpret_cast<uint32_t*>(dst + (size_t)r1 * EDIM + c) =
                pack_h2(v10 * mscale, v11 * mscale);
        } else {
            float vals[4] = {v00, v01, v10, v11};
            #pragma unroll
            for (int q = 0; q < 4; ++q) {
                int e = c + (q & 1);
                int key = (q < 2) ? r0 : r1;
                g_vt[((size_t)s * EDIM + e) * LSEQ + key] = __float2half_rn(vals[q]);
            }
        }
    }
}

// ----------------------------------------------------------------------------
// Kernel 2: flash attention (unchanged from validated round 15)
// ----------------------------------------------------------------------------
#define AT_QF   0
#define AT_K0   18432
#define AT_K1   27648
#define AT_V0   36864
#define AT_V1   48384
#define AT_RED  59904
#define AT_RED2 60928
#define AT_SMEM 61952

__device__ __forceinline__ void attn_prefetch(uint32_t sb, int buf, int s, int kt,
                                              int tid) {
    const uint32_t kb = sb + (buf ? AT_K1 : AT_K0);
    const uint32_t vb = sb + (buf ? AT_V1 : AT_V0);
    #pragma unroll
    for (int t = 0; t < 2; ++t) {
        int f = tid + t * 256;
        int rr = f >> 3, c8 = (f & 7) * 8;
        const __half* src = g_kf
            + (size_t)s * LSEQ * EDIM + (size_t)(kt * 64 + rr) * EDIM + c8;
        CP_ASYNC(kb + rr * 144 + c8 * 2, src);
    }
    #pragma unroll
    for (int t = 0; t < 2; ++t) {
        int f = tid + t * 256;
        int e = f >> 3, k8 = (f & 7) * 8;
        const __half* src = g_vt
            + ((size_t)s * EDIM + e) * LSEQ + kt * 64 + k8;
        CP_ASYNC(vb + e * 144 + k8 * 2, src);
    }
    CP_COMMIT();
}

__global__ __launch_bounds__(256, 2)
void attn_kernel()
{
    extern __shared__ char smem[];
    const uint32_t sb = smem_u32(smem);
    const int tid = threadIdx.x, wid = tid >> 5, lane = tid & 31;
    const int g = lane >> 2, tig = lane & 3;
    const int s = blockIdx.y, row0 = blockIdx.x * 128;

    attn_prefetch(sb, 0, s, 0, tid);

    for (int i = tid; i < 16 * 36 * 2; i += 256) {
        int buf = i >= 16 * 36;
        int ii = i & (16 * 36 - 1);
        int rr = 64 + ii / 36, c4 = (ii % 36) * 4;
        uint32_t val = (rr == 64) ? 0x3C003C00u : 0u;
        *reinterpret_cast<uint32_t*>(smem + (buf ? AT_V1 : AT_V0) + rr * 144 + c4) = val;
    }

    const __half* Qf = g_qf + (size_t)s * LSEQ * EDIM + (size_t)row0 * EDIM;
    #pragma unroll
    for (int t = 0; t < 4; ++t) {
        int f = tid + t * 256;
        int rr = f >> 3, c8 = (f & 7) * 8;
        *reinterpret_cast<uint4*>(smem + AT_QF + rr * 144 + c8 * 2) =
            *reinterpret_cast<const uint4*>(Qf + (size_t)rr * EDIM + c8);
    }

    float O[8][4], O5[4];
    #pragma unroll
    for (int j = 0; j < 8; ++j)
        #pragma unroll
        for (int q = 0; q < 4; ++q) O[j][q] = 0.f;
    #pragma unroll
    for (int q = 0; q < 4; ++q) O5[q] = 0.f;
    float m0 = -1e30f, m1 = -1e30f;

    for (int kt = 0; kt < LSEQ / 64; ++kt) {
        const int cur = kt & 1;
        if (kt < LSEQ / 64 - 1) {
            attn_prefetch(sb, 1 - cur, s, kt + 1, tid);
            CP_WAIT(1);
        } else {
            CP_WAIT(0);
        }
        __syncthreads();

        const uint32_t kf = sb + (cur ? AT_K1 : AT_K0);
        const uint32_t vf = sb + (cur ? AT_V1 : AT_V0);

        float S[8][4];
        #pragma unroll
        for (int nt = 0; nt < 8; ++nt)
            #pragma unroll
            for (int q = 0; q < 4; ++q) S[nt][q] = 0.f;

        #pragma unroll
        for (int kb = 0; kb < 4; ++kb) {
            const int kby = kb * 32;
            uint32_t aF[4];
            ldsm4(aF, ldsm_addr(sb + AT_QF, wid * 16, kby, 144, lane));
            #pragma unroll
            for (int ntp = 0; ntp < 4; ++ntp) {
                uint32_t bF[4];
                ldsm4(bF, ldsm_addr(kf, ntp * 16, kby, 144, lane));
                mma_f16(S[2*ntp],   aF, bF[0], bF[2]);
                mma_f16(S[2*ntp+1], aF, bF[1], bF[3]);
            }
        }

        float mx0 = -1e30f, mx1 = -1e30f;
        #pragma unroll
        for (int nt = 0; nt < 8; ++nt) {
            mx0 = fmaxf(mx0, fmaxf(S[nt][0], S[nt][1]));
            mx1 = fmaxf(mx1, fmaxf(S[nt][2], S[nt][3]));
        }
        mx0 = fmaxf(mx0, __shfl_xor_sync(0xffffffffu, mx0, 1));
        mx0 = fmaxf(mx0, __shfl_xor_sync(0xffffffffu, mx0, 2));
        mx1 = fmaxf(mx1, __shfl_xor_sync(0xffffffffu, mx1, 1));
        mx1 = fmaxf(mx1, __shfl_xor_sync(0xffffffffu, mx1, 2));
        float mn0 = fmaxf(m0, mx0), mn1 = fmaxf(m1, mx1);
        float a0 = exp2f(m0 - mn0), a1 = exp2f(m1 - mn1);
        m0 = mn0; m1 = mn1;

        #pragma unroll
        for (int j = 0; j < 8; ++j) {
            O[j][0] *= a0; O[j][1] *= a0;
            O[j][2] *= a1; O[j][3] *= a1;
        }
        O5[0] *= a0; O5[1] *= a0; O5[2] *= a1; O5[3] *= a1;

        #pragma unroll
        for (int kb = 0; kb < 4; ++kb) {
            uint32_t pf[4];
            pf[0] = pack_exp2(S[2*kb][0] - mn0,   S[2*kb][1] - mn0);
            pf[1] = pack_exp2(S[2*kb][2] - mn1,   S[2*kb][3] - mn1);
            pf[2] = pack_exp2(S[2*kb+1][0] - mn0, S[2*kb+1][1] - mn0);
            pf[3] = pack_exp2(S[2*kb+1][2] - mn1, S[2*kb+1][3] - mn1);
            const int kby = kb * 32;
            #pragma unroll
            for (int ntp = 0; ntp < 4; ++ntp) {
                uint32_t vF[4];
                ldsm4(vF, ldsm_addr(vf, ntp * 16, kby, 144, lane));
                mma_f16(O[2*ntp],   pf, vF[0], vF[2]);
                mma_f16(O[2*ntp+1], pf, vF[1], vF[3]);
            }
            uint32_t vE[4];
            ldsm4(vE, ldsm_addr(vf, 64, kby, 144, lane));
            mma_f16(O5, pf, vE[0], vE[2]);
        }
        __syncthreads();
    }

    float l0 = __shfl_sync(0xffffffffu, O5[0], lane & ~3);
    float l1 = __shfl_sync(0xffffffffu, O5[2], lane & ~3);
    const float inv0 = 1.f / l0, inv1 = 1.f / l1;
    const int r0 = row0 + wid * 16 + g, r1 = r0 + 8;
    float* Og = g_o + (size_t)s * LSEQ * EDIM;
    float lsum = 0.f, lsq = 0.f;
    #pragma unroll
    for (int j = 0; j < 8; ++j) {
        int c = tig * 2 + 8 * j;
        float o00 = O[j][0] * inv0, o01 = O[j][1] * inv0;
        float o10 = O[j][2] * inv1, o11 = O[j][3] * inv1;
        *reinterpret_cast<float2*>(Og + (size_t)r0 * EDIM + c) = make_float2(o00, o01);
        *reinterpret_cast<float2*>(Og + (size_t)r1 * EDIM + c) = make_float2(o10, o11);
        lsum += o00 + o01 + o10 + o11;
        lsq  += o00*o00 + o01*o01 + o10*o10 + o11*o11;
    }

    float* red  = reinterpret_cast<float*>(smem + AT_RED);
    float* red2 = reinterpret_cast<float*>(smem + AT_RED2);
    __syncthreads();
    red[tid] = lsum; red2[tid] = lsq;
    __syncthreads();
    #pragma unroll
    for (int st = 128; st; st >>= 1) {
        if (tid < st) { red[tid] += red[tid + st]; red2[tid] += red2[tid + st]; }
        __syncthreads();
    }
    if (tid == 0) g_part[s * NQT + blockIdx.x] = make_float2(red[0], red2[0]);
}

// ---------------- kernel 3: fused stats + normalize (2 float4/thread) ----------------
__global__ void norm_kernel(float* __restrict__ out)
{
    __shared__ float2 st_sh;
    const int blk = blockIdx.x;
    const int s = blk >> 6;                     // 2048 floats/block, 64 blocks/slice
    if (threadIdx.x < 32) {
        float sum = 0.f, sq = 0.f;
        if (threadIdx.x < NQT) {
            float2 p = g_part[s * NQT + threadIdx.x];
            sum = p.x; sq = p.y;
        }
        #pragma unroll
        for (int off = 16; off; off >>= 1) {
            sum += __shfl_xor_sync(0xffffffffu, sum, off);
            sq  += __shfl_xor_sync(0xffffffffu, sq,  off);
        }
        if (threadIdx.x == 0) {
            const float n = (float)(LSEQ * EDIM);
            float mu = sum / n;
            float var = sq / n - mu * mu;
            st_sh = make_float2(mu, rsqrtf(var + EPS));
        }
    }
    __syncthreads();
    float2 st = st_sh;
    int base0 = blk * 2048 + threadIdx.x * 4;
    #pragma unroll
    for (int h = 0; h < 2; ++h) {
        int base = base0 + h * 1024;
        const float4 o = *reinterpret_cast<const float4*>(&g_o[base]);
        float4 rr;
        rr.x = (o.x - st.x) * st.y; rr.y = (o.y - st.x) * st.y;
        rr.z = (o.z - st.x) * st.y; rr.w = (o.w - st.x) * st.y;
        *reinterpret_cast<float4*>(&out[base]) = rr;
    }
}

// ---------------- host ----------------
extern "C" void kernel_launch(void* const* d_in, const int* in_sizes, int n_in,
                              void* d_out, int out_size)
{
    const float* info = (const float*)d_in[0];
    const float* Wq = (const float*)d_in[1];
    const float* bq = (const float*)d_in[2];
    const float* Wk = (const float*)d_in[3];
    const float* bk = (const float*)d_in[4];
    const float* Wv = (const float*)d_in[5];
    const float* bv = (const float*)d_in[6];
    float* out = (float*)d_out;

    cudaFuncSetAttribute(proj_kernel, cudaFuncAttributeMaxDynamicSharedMemorySize, PR_SMEM);
    cudaFuncSetAttribute(attn_kernel, cudaFuncAttributeMaxDynamicSharedMemorySize, AT_SMEM);

    wsplit_kernel<<<(3 * EDIM * DLLM + 255) / 256, 256>>>(Wq, Wk, Wv);
    proj_kernel<<<dim3(3 * (LSEQ / 128), NSLICE), 256, PR_SMEM>>>(info, bq, bk, bv);
    attn_kernel<<<dim3(NQT, NSLICE), 256, AT_SMEM>>>();
    norm_kernel<<<NSLICE * LSEQ * EDIM / 2048, 256>>>(out);
}

// round 17
// speedup vs baseline: 1.0295x; 1.0295x over previous
#include <cuda_runtime.h>
#include <cuda_fp16.h>
#include <math.h>
#include <stdint.h>

#define NSLICE 16
#define LSEQ   2048
#define DLLM   768
#define EDIM   64
#define EPS    1e-5f
#define NQT    16
#define QLOG2SCALE (0.125f * 1.4426950408889634f)

// ---------------- device scratch ----------------
__device__ float g_o[NSLICE*LSEQ*EDIM];
__device__ __half g_qf[NSLICE*LSEQ*EDIM];    // q*0.125*log2e fp16
__device__ __half g_kf[NSLICE*LSEQ*EDIM];    // k fp16
__device__ __half g_vt[NSLICE*EDIM*LSEQ];    // V^T [s][e][key] fp16
__device__ __half g_wf[3*EDIM*DLLM];         // W^T [w][n][k] fp16
__device__ float2 g_part[NSLICE*NQT];

// ---------------- helpers (validated) ----------------
__device__ __forceinline__ uint32_t smem_u32(const void* p) {
    uint32_t a;
    asm("{ .reg .u64 t; cvta.to.shared.u64 t, %1; cvt.u32.u64 %0, t; }" : "=r"(a) : "l"(p));
    return a;
}
__device__ __forceinline__ void ldsm4(uint32_t* r, uint32_t addr) {
    asm volatile("ldmatrix.sync.aligned.m8n8.x4.shared.b16 {%0,%1,%2,%3}, [%4];"
                 : "=r"(r[0]), "=r"(r[1]), "=r"(r[2]), "=r"(r[3]) : "r"(addr) : "memory");
}
__device__ __forceinline__ uint32_t ldsm_addr(uint32_t base, int row0, int kbyte,
                                              int pitch, int lane) {
    return base + (row0 + (lane & 15)) * pitch + kbyte + (lane >> 4) * 16;
}
__device__ __forceinline__ void mma_f16(float* d, const uint32_t* a,
                                        uint32_t b0, uint32_t b1) {
    asm volatile("mma.sync.aligned.m16n8k16.row.col.f32.f16.f16.f32 "
        "{%0,%1,%2,%3}, {%4,%5,%6,%7}, {%8,%9}, {%0,%1,%2,%3};"
        : "+f"(d[0]), "+f"(d[1]), "+f"(d[2]), "+f"(d[3])
        : "r"(a[0]), "r"(a[1]), "r"(a[2]), "r"(a[3]), "r"(b0), "r"(b1));
}
__device__ __forceinline__ uint32_t pack_h2(float x0, float x1) {
    __half2 h = __floats2half2_rn(x0, x1);
    return *reinterpret_cast<uint32_t*>(&h);
}
__device__ __forceinline__ uint32_t pack_exp2(float x0, float x1) {
    __half2 h = h2exp2(__floats2half2_rn(x0, x1));
    return *reinterpret_cast<uint32_t*>(&h);
}
#define CP_ASYNC(dst, src) \
    asm volatile("cp.async.cg.shared.global [%0], [%1], 16;" :: "r"(dst), "l"(src) : "memory")
#define CP_COMMIT() asm volatile("cp.async.commit_group;" ::: "memory")
#define CP_WAIT(n)  asm volatile("cp.async.wait_group %0;" :: "n"(n) : "memory")

// ---------------- kernel 0: W^T fp16 ----------------
__global__ void wsplit_kernel(const float* __restrict__ Wq,
                              const float* __restrict__ Wk,
                              const float* __restrict__ Wv) {
    int idx = blockIdx.x * 256 + threadIdx.x;
    if (idx >= 3 * EDIM * DLLM) return;
    int w = idx / (EDIM * DLLM), rem = idx % (EDIM * DLLM);
    int n = rem / DLLM, k = rem % DLLM;
    const float* W = (w == 0) ? Wq : (w == 1) ? Wk : Wv;
    g_wf[idx] = __float2half_rn(W[k * EDIM + n]);
}

// ----------------------------------------------------------------------------
// Kernel 1: FUSED projection (q|k|v per CTA — X read once). 256 CTAs, occ 2.
// CTA = 128 rows x 192 cols; K chunked by 64; in-loop LDG->cvt->STS for A;
// B (3 weights) double-buffered via cp.async.
// ----------------------------------------------------------------------------
#define PA0 0              /* 128 x 144 fp16 = 18432 */
#define PA1 18432
#define PB0 36864          /* 3 x 9216 = 27648 */
#define PB1 64512
#define PR_SMEM 92160

__global__ __launch_bounds__(256, 2)
void proj_kernel(const float* __restrict__ X,
                 const float* __restrict__ bq, const float* __restrict__ bk,
                 const float* __restrict__ bv)
{
    extern __shared__ char smem[];
    const uint32_t sb = smem_u32(smem);
    const int tid = threadIdx.x, wid = tid >> 5, lane = tid & 31;
    const int g = lane >> 2, tig = lane & 3;
    const int s = blockIdx.y;
    const int row0 = blockIdx.x * 128;
    const float* Xs = X + (size_t)s * LSEQ * DLLM + (size_t)row0 * DLLM;

    float acc[3][8][4];
    #pragma unroll
    for (int w = 0; w < 3; ++w)
        #pragma unroll
        for (int j = 0; j < 8; ++j)
            #pragma unroll
            for (int q = 0; q < 4; ++q) acc[w][j][q] = 0.f;

    // B chunk 0 (3 weights x 512 16B chunks = 1536, 6/thread)
    #pragma unroll
    for (int t = 0; t < 6; ++t) {
        int f = tid + t * 256;
        int iw = f >> 9, rem = f & 511;
        int n = rem >> 3, k8 = (rem & 7) * 8;
        CP_ASYNC(sb + PB0 + iw * 9216 + n * 144 + k8 * 2,
                 g_wf + (size_t)iw * EDIM * DLLM + (size_t)n * DLLM + k8);
    }
    CP_COMMIT();

    for (int chunk = 0; chunk < 12; ++chunk) {
        const int cur = chunk & 1;
        const uint32_t ab = sb + (cur ? PA1 : PA0);
        const uint32_t bb = sb + (cur ? PB1 : PB0);
        const int k0 = chunk * 64;

        // A: LDG fp32 -> cvt -> STS (2048 float4, 8/thread)
        #pragma unroll
        for (int t = 0; t < 8; ++t) {
            int f = tid + t * 256;
            int rr = f >> 4, c4 = (f & 15) * 4;
            float4 x = *reinterpret_cast<const float4*>(&Xs[(size_t)rr * DLLM + k0 + c4]);
            *reinterpret_cast<uint2*>(smem + (cur ? PA1 : PA0) + rr * 144 + c4 * 2) =
                make_uint2(pack_h2(x.x, x.y), pack_h2(x.z, x.w));
        }
        // next B
        if (chunk < 11) {
            const int k0n = k0 + 64;
            const uint32_t bbn = sb + (cur ? PB0 : PB1);
            #pragma unroll
            for (int t = 0; t < 6; ++t) {
                int f = tid + t * 256;
                int iw = f >> 9, rem = f & 511;
                int n = rem >> 3, k8 = (rem & 7) * 8;
                CP_ASYNC(bbn + iw * 9216 + n * 144 + k8 * 2,
                         g_wf + (size_t)iw * EDIM * DLLM + (size_t)n * DLLM + k0n + k8);
            }
            CP_COMMIT();
            CP_WAIT(1);
        } else {
            CP_WAIT(0);
        }
        __syncthreads();

        #pragma unroll
        for (int kb = 0; kb < 4; ++kb) {
            const int kby = kb * 32;
            uint32_t aF[4];
            ldsm4(aF, ldsm_addr(ab, wid * 16, kby, 144, lane));
            #pragma unroll
            for (int w = 0; w < 3; ++w) {
                const uint32_t bwb = bb + w * 9216;
                #pragma unroll
                for (int ntp = 0; ntp < 4; ++ntp) {
                    uint32_t bF[4];
                    ldsm4(bF, ldsm_addr(bwb, ntp * 16, kby, 144, lane));
                    mma_f16(acc[w][2*ntp],   aF, bF[0], bF[2]);
                    mma_f16(acc[w][2*ntp+1], aF, bF[1], bF[3]);
                }
            }
        }
        __syncthreads();
    }

    // epilogue (validated mapping): rows r0,r1; cols 2*tig+8j
    const int r0 = row0 + wid * 16 + g, r1 = r0 + 8;
    #pragma unroll
    for (int w = 0; w < 3; ++w) {
        const float* bias = (w == 0) ? bq : (w == 1) ? bk : bv;
        const float mscale = (w == 0) ? QLOG2SCALE : 1.f;
        #pragma unroll
        for (int j = 0; j < 8; ++j) {
            int c = tig * 2 + 8 * j;
            float b0 = bias[c], b1 = bias[c + 1];
            float v00 = acc[w][j][0] + b0, v01 = acc[w][j][1] + b1;
            float v10 = acc[w][j][2] + b0, v11 = acc[w][j][3] + b1;
            if (w < 2) {
                __half* dst = (w ? g_kf : g_qf) + (size_t)s * LSEQ * EDIM;
                *reinterpret_cast<uint32_t*>(dst + (size_t)r0 * EDIM + c) =
                    pack_h2(v00 * mscale, v01 * mscale);
                *reinterpret_cast<uint32_t*>(dst + (size_t)r1 * EDIM + c) =
                    pack_h2(v10 * mscale, v11 * mscale);
            } else {
                float vals[4] = {v00, v01, v10, v11};
                #pragma unroll
                for (int q = 0; q < 4; ++q) {
                    int e = c + (q & 1);
                    int key = (q < 2) ? r0 : r1;
                    g_vt[((size_t)s * EDIM + e) * LSEQ + key] = __float2half_rn(vals[q]);
                }
            }
        }
    }
}

// ----------------------------------------------------------------------------
// Kernel 2: flash attention (unchanged, validated round 15)
// ----------------------------------------------------------------------------
#define AT_QF   0
#define AT_K0   18432
#define AT_K1   27648
#define AT_V0   36864
#define AT_V1   48384
#define AT_RED  59904
#define AT_RED2 60928
#define AT_SMEM 61952

__device__ __forceinline__ void attn_prefetch(uint32_t sb, int buf, int s, int kt,
                                              int tid) {
    const uint32_t kb = sb + (buf ? AT_K1 : AT_K0);
    const uint32_t vb = sb + (buf ? AT_V1 : AT_V0);
    #pragma unroll
    for (int t = 0; t < 2; ++t) {
        int f = tid + t * 256;
        int rr = f >> 3, c8 = (f & 7) * 8;
        const __half* src = g_kf
            + (size_t)s * LSEQ * EDIM + (size_t)(kt * 64 + rr) * EDIM + c8;
        CP_ASYNC(kb + rr * 144 + c8 * 2, src);
    }
    #pragma unroll
    for (int t = 0; t < 2; ++t) {
        int f = tid + t * 256;
        int e = f >> 3, k8 = (f & 7) * 8;
        const __half* src = g_vt
            + ((size_t)s * EDIM + e) * LSEQ + kt * 64 + k8;
        CP_ASYNC(vb + e * 144 + k8 * 2, src);
    }
    CP_COMMIT();
}

__global__ __launch_bounds__(256, 2)
void attn_kernel()
{
    extern __shared__ char smem[];
    const uint32_t sb = smem_u32(smem);
    const int tid = threadIdx.x, wid = tid >> 5, lane = tid & 31;
    const int g = lane >> 2, tig = lane & 3;
    const int s = blockIdx.y, row0 = blockIdx.x * 128;

    attn_prefetch(sb, 0, s, 0, tid);

    for (int i = tid; i < 16 * 36 * 2; i += 256) {
        int buf = i >= 16 * 36;
        int ii = i & (16 * 36 - 1);
        int rr = 64 + ii / 36, c4 = (ii % 36) * 4;
        uint32_t val = (rr == 64) ? 0x3C003C00u : 0u;
        *reinterpret_cast<uint32_t*>(smem + (buf ? AT_V1 : AT_V0) + rr * 144 + c4) = val;
    }

    const __half* Qf = g_qf + (size_t)s * LSEQ * EDIM + (size_t)row0 * EDIM;
    #pragma unroll
    for (int t = 0; t < 4; ++t) {
        int f = tid + t * 256;
        int rr = f >> 3, c8 = (f & 7) * 8;
        *reinterpret_cast<uint4*>(smem + AT_QF + rr * 144 + c8 * 2) =
            *reinterpret_cast<const uint4*>(Qf + (size_t)rr * EDIM + c8);
    }

    float O[8][4], O5[4];
    #pragma unroll
    for (int j = 0; j < 8; ++j)
        #pragma unroll
        for (int q = 0; q < 4; ++q) O[j][q] = 0.f;
    #pragma unroll
    for (int q = 0; q < 4; ++q) O5[q] = 0.f;
    float m0 = -1e30f, m1 = -1e30f;

    for (int kt = 0; kt < LSEQ / 64; ++kt) {
        const int cur = kt & 1;
        if (kt < LSEQ / 64 - 1) {
            attn_prefetch(sb, 1 - cur, s, kt + 1, tid);
            CP_WAIT(1);
        } else {
            CP_WAIT(0);
        }
        __syncthreads();

        const uint32_t kf = sb + (cur ? AT_K1 : AT_K0);
        const uint32_t vf = sb + (cur ? AT_V1 : AT_V0);

        float S[8][4];
        #pragma unroll
        for (int nt = 0; nt < 8; ++nt)
            #pragma unroll
            for (int q = 0; q < 4; ++q) S[nt][q] = 0.f;

        #pragma unroll
        for (int kb = 0; kb < 4; ++kb) {
            const int kby = kb * 32;
            uint32_t aF[4];
            ldsm4(aF, ldsm_addr(sb + AT_QF, wid * 16, kby, 144, lane));
            #pragma unroll
            for (int ntp = 0; ntp < 4; ++ntp) {
                uint32_t bF[4];
                ldsm4(bF, ldsm_addr(kf, ntp * 16, kby, 144, lane));
                mma_f16(S[2*ntp],   aF, bF[0], bF[2]);
                mma_f16(S[2*ntp+1], aF, bF[1], bF[3]);
            }
        }

        float mx0 = -1e30f, mx1 = -1e30f;
        #pragma unroll
        for (int nt = 0; nt < 8; ++nt) {
            mx0 = fmaxf(mx0, fmaxf(S[nt][0], S[nt][1]));
            mx1 = fmaxf(mx1, fmaxf(S[nt][2], S[nt][3]));
        }
        mx0 = fmaxf(mx0, __shfl_xor_sync(0xffffffffu, mx0, 1));
        mx0 = fmaxf(mx0, __shfl_xor_sync(0xffffffffu, mx0, 2));
        mx1 = fmaxf(mx1, __shfl_xor_sync(0xffffffffu, mx1, 1));
        mx1 = fmaxf(mx1, __shfl_xor_sync(0xffffffffu, mx1, 2));
        float mn0 = fmaxf(m0, mx0), mn1 = fmaxf(m1, mx1);
        float a0 = exp2f(m0 - mn0), a1 = exp2f(m1 - mn1);
        m0 = mn0; m1 = mn1;

        #pragma unroll
        for (int j = 0; j < 8; ++j) {
            O[j][0] *= a0; O[j][1] *= a0;
            O[j][2] *= a1; O[j][3] *= a1;
        }
        O5[0] *= a0; O5[1] *= a0; O5[2] *= a1; O5[3] *= a1;

        #pragma unroll
        for (int kb = 0; kb < 4; ++kb) {
            uint32_t pf[4];
            pf[0] = pack_exp2(S[2*kb][0] - mn0,   S[2*kb][1] - mn0);
            pf[1] = pack_exp2(S[2*kb][2] - mn1,   S[2*kb][3] - mn1);
            pf[2] = pack_exp2(S[2*kb+1][0] - mn0, S[2*kb+1][1] - mn0);
            pf[3] = pack_exp2(S[2*kb+1][2] - mn1, S[2*kb+1][3] - mn1);
            const int kby = kb * 32;
            #pragma unroll
            for (int ntp = 0; ntp < 4; ++ntp) {
                uint32_t vF[4];
                ldsm4(vF, ldsm_addr(vf, ntp * 16, kby, 144, lane));
                mma_f16(O[2*ntp],   pf, vF[0], vF[2]);
                mma_f16(O[2*ntp+1], pf, vF[1], vF[3]);
            }
            uint32_t vE[4];
            ldsm4(vE, ldsm_addr(vf, 64, kby, 144, lane));
            mma_f16(O5, pf, vE[0], vE[2]);
        }
        __syncthreads();
    }

    float l0 = __shfl_sync(0xffffffffu, O5[0], lane & ~3);
    float l1 = __shfl_sync(0xffffffffu, O5[2], lane & ~3);
    const float inv0 = 1.f / l0, inv1 = 1.f / l1;
    const int r0 = row0 + wid * 16 + g, r1 = r0 + 8;
    float* Og = g_o + (size_t)s * LSEQ * EDIM;
    float lsum = 0.f, lsq = 0.f;
    #pragma unroll
    for (int j = 0; j < 8; ++j) {
        int c = tig * 2 + 8 * j;
        float o00 = O[j][0] * inv0, o01 = O[j][1] * inv0;
        float o10 = O[j][2] * inv1, o11 = O[j][3] * inv1;
        *reinterpret_cast<float2*>(Og + (size_t)r0 * EDIM + c) = make_float2(o00, o01);
        *reinterpret_cast<float2*>(Og + (size_t)r1 * EDIM + c) = make_float2(o10, o11);
        lsum += o00 + o01 + o10 + o11;
        lsq  += o00*o00 + o01*o01 + o10*o10 + o11*o11;
    }

    float* red  = reinterpret_cast<float*>(smem + AT_RED);
    float* red2 = reinterpret_cast<float*>(smem + AT_RED2);
    __syncthreads();
    red[tid] = lsum; red2[tid] = lsq;
    __syncthreads();
    #pragma unroll
    for (int st = 128; st; st >>= 1) {
        if (tid < st) { red[tid] += red[tid + st]; red2[tid] += red2[tid + st]; }
        __syncthreads();
    }
    if (tid == 0) g_part[s * NQT + blockIdx.x] = make_float2(red[0], red2[0]);
}

// ---------------- kernel 3: fused stats + normalize ----------------
__global__ void norm_kernel(float* __restrict__ out)
{
    __shared__ float2 st_sh;
    const int blk = blockIdx.x;
    const int s = blk >> 6;
    if (threadIdx.x < 32) {
        float sum = 0.f, sq = 0.f;
        if (threadIdx.x < NQT) {
            float2 p = g_part[s * NQT + threadIdx.x];
            sum = p.x; sq = p.y;
        }
        #pragma unroll
        for (int off = 16; off; off >>= 1) {
            sum += __shfl_xor_sync(0xffffffffu, sum, off);
            sq  += __shfl_xor_sync(0xffffffffu, sq,  off);
        }
        if (threadIdx.x == 0) {
            const float n = (float)(LSEQ * EDIM);
            float mu = sum / n;
            float var = sq / n - mu * mu;
            st_sh = make_float2(mu, rsqrtf(var + EPS));
        }
    }
    __syncthreads();
    float2 st = st_sh;
    int base0 = blk * 2048 + threadIdx.x * 4;
    #pragma unroll
    for (int h = 0; h < 2; ++h) {
        int base = base0 + h * 1024;
        const float4 o = *reinterpret_cast<const float4*>(&g_o[base]);
        float4 rr;
        rr.x = (o.x - st.x) * st.y; rr.y = (o.y - st.x) * st.y;
        rr.z = (o.z - st.x) * st.y; rr.w = (o.w - st.x) * st.y;
        *reinterpret_cast<float4*>(&out[base]) = rr;
    }
}

// ---------------- host ----------------
extern "C" void kernel_launch(void* const* d_in, const int* in_sizes, int n_in,
                              void* d_out, int out_size)
{
    const float* info = (const float*)d_in[0];
    const float* Wq = (const float*)d_in[1];
    const float* bq = (const float*)d_in[2];
    const float* Wk = (const float*)d_in[3];
    const float* bk = (const float*)d_in[4];
    const float* Wv = (const float*)d_in[5];
    const float* bv = (const float*)d_in[6];
    float* out = (float*)d_out;

    cudaFuncSetAttribute(proj_kernel, cudaFuncAttributeMaxDynamicSharedMemorySize, PR_SMEM);
    cudaFuncSetAttribute(attn_kernel, cudaFuncAttributeMaxDynamicSharedMemorySize, AT_SMEM);

    wsplit_kernel<<<(3 * EDIM * DLLM + 255) / 256, 256>>>(Wq, Wk, Wv);
    proj_kernel<<<dim3(LSEQ / 128, NSLICE), 256, PR_SMEM>>>(info, bq, bk, bv);
    attn_kernel<<<dim3(NQT, NSLICE), 256, AT_SMEM>>>();
    norm_kernel<<<NSLICE * LSEQ * EDIM / 2048, 256>>>(out);
}